// round 10
// baseline (speedup 1.0000x reference)
#include <cuda_runtime.h>

#define C_FEAT 64
#define NXc 432
#define NYc 496
#define S_CELLS (NXc * NYc)      // 214272 cells per batch element
#define SQ4 (S_CELLS / 4)        // float4 groups per batch/channel row (53568, % 64 == 0)
#define MAXB 8

// Scratch: cell -> (local pillar index + 1), 0 = empty.
// Zero-initialized at module load; gather_kernel restores zeros after use,
// so the empty-map invariant holds before every kernel_launch call.
__device__ unsigned short g_map16[MAXB * S_CELLS];

// Fused: scatter coords -> map, and warm L2 with the whole feat tensor.
// grid covers max(P, nfeat4) threads.
__global__ void prep_kernel(const int* __restrict__ coords,
                            const float4* __restrict__ feat4,
                            int P, int Ppb, int ncells, int nfeat4) {
    int i = blockIdx.x * blockDim.x + threadIdx.x;

    if (i < nfeat4) {
        // L2-allocating touch; volatile asm so it can't be dead-code-eliminated.
        float a, b, c, d;
        asm volatile("ld.global.cg.v4.f32 {%0,%1,%2,%3}, [%4];"
                     : "=f"(a), "=f"(b), "=f"(c), "=f"(d)
                     : "l"(feat4 + i));
    }

    if (i < P) {
        int4 c = ((const int4*)coords)[i];   // (b, z, y, x) int32
        int flat = c.x * S_CELLS + c.y + c.z * NXc + c.w;
        int local = i - c.x * Ppb;           // per-batch pillar index
        if (flat >= 0 && flat < ncells && local >= 0 && local < 0xFFFF) {
            g_map16[flat] = (unsigned short)(local + 1);
        }
    }
}

// R7 shape (best measured): block (64, 4): x = spatial float4-group,
// y = channel slice (16 channels each). Grid covers B*SQ4 exactly.
__global__ void __launch_bounds__(256) gather_kernel(
    const float* __restrict__ feat,     // [P, 64]
    float4* __restrict__ out4,          // [B, 64, SQ4] float4
    int Ppb)
{
    int t = blockIdx.x * 64 + threadIdx.x;   // global q-group index
    int s = threadIdx.y;                     // channel slice 0..3

    int b = t / SQ4;
    int q = t - b * SQ4;

    // One 8B load = 4 uint16 map entries (0 = empty, else local+1)
    uint2* mp = ((uint2*)(g_map16 + b * S_CELLS)) + q;
    uint2 mraw = *mp;

    // All 4 slices read before slice 0 resets.
    __syncthreads();
    if (s == 0 && (mraw.x | mraw.y)) {
        *mp = make_uint2(0u, 0u);
    }

    unsigned m0 = mraw.x & 0xFFFFu, m1 = mraw.x >> 16;
    unsigned m2 = mraw.y & 0xFFFFu, m3 = mraw.y >> 16;

    size_t pbase = (size_t)b * (size_t)Ppb;
    const float4* f0 = (const float4*)(feat + (pbase + m0 - 1) * C_FEAT);
    const float4* f1 = (const float4*)(feat + (pbase + m1 - 1) * C_FEAT);
    const float4* f2 = (const float4*)(feat + (pbase + m2 - 1) * C_FEAT);
    const float4* f3 = (const float4*)(feat + (pbase + m3 - 1) * C_FEAT);

    float4* o = out4 + (size_t)b * C_FEAT * SQ4 + q;

    const float4 z4 = make_float4(0.f, 0.f, 0.f, 0.f);

#pragma unroll
    for (int i = 0; i < 4; ++i) {
        int c4 = 4 * s + i;                 // this slice's float4-channel-group
        // plain derefs -> predicated LDG (no branches); should hit warm L2
        float4 a  = (m0 != 0u) ? f0[c4] : z4;
        float4 bb = (m1 != 0u) ? f1[c4] : z4;
        float4 cc = (m2 != 0u) ? f2[c4] : z4;
        float4 dd = (m3 != 0u) ? f3[c4] : z4;

        // 4x4 register transpose: warp writes 32 consecutive float4 (512B) per row
        __stcs(o + (size_t)(4 * c4 + 0) * SQ4, make_float4(a.x, bb.x, cc.x, dd.x));
        __stcs(o + (size_t)(4 * c4 + 1) * SQ4, make_float4(a.y, bb.y, cc.y, dd.y));
        __stcs(o + (size_t)(4 * c4 + 2) * SQ4, make_float4(a.z, bb.z, cc.z, dd.z));
        __stcs(o + (size_t)(4 * c4 + 3) * SQ4, make_float4(a.w, bb.w, cc.w, dd.w));
    }
}

extern "C" void kernel_launch(void* const* d_in, const int* in_sizes, int n_in,
                              void* d_out, int out_size) {
    const float* feat   = (const float*)d_in[0];
    const int*   coords = (const int*)d_in[1];

    int P = in_sizes[0] / C_FEAT;                 // number of pillars
    int B = out_size / (C_FEAT * S_CELLS);        // batch size from output shape
    if (B > MAXB) B = MAXB;
    int Ppb = P / B;

    int ncells = B * S_CELLS;
    int nfeat4 = in_sizes[0] / 4;                 // float4 count of feat
    int nprep = nfeat4 > P ? nfeat4 : P;
    prep_kernel<<<(nprep + 255) / 256, 256>>>(coords, (const float4*)feat,
                                              P, Ppb, ncells, nfeat4);

    dim3 blk(64, 4);
    int nblocks = (B * SQ4) / 64;                 // exact: SQ4 % 64 == 0
    gather_kernel<<<nblocks, blk>>>(feat, (float4*)d_out, Ppb);
}